// round 16
// baseline (speedup 1.0000x reference)
#include <cuda_runtime.h>
#include <cuda_fp16.h>
#include <cstdint>
#include <math.h>

#define DO_   30
#define TPB   256

// ---------------- device scratch (no runtime alloc) ----------------
__device__ __align__(16) __half g_xt[16 * 32 * 32 * 32 * 16];   // [b][d][h][w][cin]
__device__ __align__(16) __half g_w2[27 * 32 * 16];             // [tap][cout][cin]

// ---------------- helpers ----------------
__device__ __forceinline__ uint32_t smem_u32(const void* p) {
    uint32_t a;
    asm("{ .reg .u64 t; cvta.to.shared.u64 t, %1; cvt.u32.u64 %0, t; }" : "=r"(a) : "l"(p));
    return a;
}
__device__ __forceinline__ void cp_async16(uint32_t sdst, const void* gsrc) {
    asm volatile("cp.async.cg.shared.global [%0], [%1], 16;\n" :: "r"(sdst), "l"(gsrc));
}
__device__ __forceinline__ void cp_commit() { asm volatile("cp.async.commit_group;\n" ::: "memory"); }
template<int N> __device__ __forceinline__ void cp_wait() {
    asm volatile("cp.async.wait_group %0;\n" :: "n"(N) : "memory");
}
__device__ __forceinline__ void ldsm4(uint32_t* r, uint32_t addr) {
    asm volatile("ldmatrix.sync.aligned.m8n8.x4.shared.b16 {%0,%1,%2,%3}, [%4];"
        : "=r"(r[0]), "=r"(r[1]), "=r"(r[2]), "=r"(r[3]) : "r"(addr));
}
// fp16-accumulator MMA: D(f16x4 in 2 regs) = A*B + C
__device__ __forceinline__ void mma_f16acc(uint32_t* d, const uint32_t* a, const uint32_t* b,
                                           uint32_t c0, uint32_t c1) {
    asm volatile(
        "mma.sync.aligned.m16n8k16.row.col.f16.f16.f16.f16 "
        "{%0,%1}, {%2,%3,%4,%5}, {%6,%7}, {%8,%9};"
        : "=r"(d[0]), "=r"(d[1])
        : "r"(a[0]), "r"(a[1]), "r"(a[2]), "r"(a[3]), "r"(b[0]), "r"(b[1]),
          "r"(c0), "r"(c1));
}

// Swizzle: row's two 16B chunks at chunk ^ ((row>>2)&1) -> conflict-free ldmatrix.
__device__ __forceinline__ uint32_t swz(uint32_t row, uint32_t chunk16) {
    return row * 32u + (chunk16 ^ ((row & 4u) << 2));
}

// ---------------- transform kernel (no smem, fully coalesced) ----------------
__global__ __launch_bounds__(256) void xform_all(const float* __restrict__ x,
                                                 const float* __restrict__ w)
{
    const int t = threadIdx.x;
    if (blockIdx.x < 2048) {
        const int blk = blockIdx.x;
        const int b = blk >> 7, d = (blk >> 2) & 31, hg = blk & 3;
        const int h = hg * 8 + (t >> 5);
        const int ww = t & 31;

        const float* xp = x + ((long)(b * 16) << 15) + (d << 10) + (h << 5) + ww;
        float v[16];
        #pragma unroll
        for (int c = 0; c < 16; ++c)
            v[c] = xp[(long)c << 15];

        uint32_t r[8];
        #pragma unroll
        for (int k = 0; k < 8; ++k) {
            __half2 p = __floats2half2_rn(v[2 * k], v[2 * k + 1]);
            r[k] = *(uint32_t*)&p;
        }
        uint4* pdst = (uint4*)&g_xt[((long)(b * 32 + d) << 14) + (h << 9) + (ww << 4)];
        pdst[0] = make_uint4(r[0], r[1], r[2], r[3]);
        pdst[1] = make_uint4(r[4], r[5], r[6], r[7]);
    } else {
        const int idx = (blockIdx.x - 2048) * 256 + t;
        if (idx < 27 * 512) {
            const int tap = idx >> 9, r = idx & 511;
            const int co = r >> 4, cin = r & 15;
            g_w2[tap * 512 + r] = __float2half_rn(w[(co * 16 + cin) * 27 + tap]);
        }
    }
}

// ---------------- main kernel ----------------
// M = 512 rows per CTA; 8 warps x 4 rowtiles. 32B pitch + XOR swizzle.
// fp16 MMA accumulators over 3-tap chunks (K=48), promoted to fp32 (9x).
#define SMEM_DYN 83136
#define SLAB0    27648
#define SLCSZ    18496

__global__ __launch_bounds__(TPB, 2) void conv_main(
    const float* __restrict__ cbias,
    const float* __restrict__ sfac,
    const float* __restrict__ bparm,
    float* __restrict__ out)
{
    extern __shared__ char sm[];
    __shared__ float e0[32], e1[32], e2n[32];

    const int d0 = blockIdx.x, b = blockIdx.y, hh = blockIdx.z;
    const int t = threadIdx.x, warp = t >> 5, lane = t & 31;
    const uint32_t smb = smem_u32(sm);
    const uint32_t ws_a = smb;
    const uint32_t sl_a = smb + SLAB0;

    const int hstart = hh * 16;
    const int rows_h = hh ? 16 : 18;
    const int chunks = rows_h * 64;

    // ---- async loads: G0 = weights + slice0; G1 = slice1; G2 = slice2
    for (int i = t; i < 1728; i += TPB)
        cp_async16(ws_a + swz((uint32_t)(i >> 1), (uint32_t)(i & 1) << 4),
                   (const char*)g_w2 + (long)i * 16);
    #pragma unroll
    for (int d = 0; d < 3; ++d) {
        const long bo = (long)((b * 32 + d0 + d) * 32 + hstart) * 1024;
        const uint32_t dh = sl_a + (uint32_t)d * SLCSZ;
        for (int i = t; i < chunks; i += TPB)
            cp_async16(dh + swz((uint32_t)(i >> 1), (uint32_t)(i & 1) << 4),
                       (const char*)g_xt + bo + (long)i * 16);
        cp_commit();
    }

    if (t < 32) {
        const float s = sfac[t];
        e0[t] = cbias[t] * s;
        e1[t] = s;
        e2n[t] = -1.4426950408889634f * bparm[t];
    }

    float acc[4][4][4];
    #pragma unroll
    for (int rt = 0; rt < 4; ++rt)
        #pragma unroll
        for (int j = 0; j < 4; ++j)
            #pragma unroll
            for (int k = 0; k < 4; ++k)
                acc[rt][j][k] = 0.0f;

    const uint32_t bn = (lane & 7) + ((lane & 16) >> 1);
    const uint32_t bc = (lane & 8) * 2;
    const uint32_t ar = (lane & 15);
    const uint32_t ac = (lane & 16);

    const uint32_t bofs  = swz(bn, bc);
    const uint32_t bofs2 = swz(bn + 16u, bc);
    const uint32_t awbase = (uint32_t)(warp * 64) + ar;

    uint32_t bh[4][2];
    uint32_t cacc[4][4][2];     // fp16 chunk accumulators

    #pragma unroll
    for (int kd = 0; kd < 3; ++kd) {
        if (kd == 0) cp_wait<2>(); else if (kd == 1) cp_wait<1>(); else cp_wait<0>();
        __syncthreads();

        const uint32_t kd_a = sl_a + (uint32_t)kd * SLCSZ;

        #pragma unroll
        for (int ch = 0; ch < 3; ++ch) {
            #pragma unroll
            for (int s = 0; s < 3; ++s) {
                const int t9 = ch * 3 + s;
                const int tap = kd * 9 + t9;
                const int kh = t9 / 3, kw = t9 - kh * 3;

                // B fragments for current tap
                {
                    const uint32_t base = ws_a + (uint32_t)tap * 1024u;
                    uint32_t r0[4], r1[4];
                    ldsm4(r0, base + bofs);
                    ldsm4(r1, base + bofs2);
                    bh[0][0] = r0[0]; bh[0][1] = r0[1]; bh[1][0] = r0[2]; bh[1][1] = r0[3];
                    bh[2][0] = r1[0]; bh[2][1] = r1[1]; bh[3][0] = r1[2]; bh[3][1] = r1[3];
                }

                const uint32_t arow0 = awbase + (uint32_t)(kh * 32 + kw);
                const uint32_t axor = ac ^ ((arow0 & 4u) << 2);
                #pragma unroll
                for (int rt = 0; rt < 4; ++rt) {
                    uint32_t ah[4];
                    ldsm4(ah, kd_a + (arow0 + (uint32_t)rt * 16u) * 32u + axor);
                    #pragma unroll
                    for (int j = 0; j < 4; ++j) {
                        if (s == 0)
                            mma_f16acc(cacc[rt][j], ah, bh[j], 0u, 0u);
                        else
                            mma_f16acc(cacc[rt][j], ah, bh[j], cacc[rt][j][0], cacc[rt][j][1]);
                    }
                }
            }

            // promote fp16 chunk accumulators into fp32
            #pragma unroll
            for (int rt = 0; rt < 4; ++rt)
                #pragma unroll
                for (int j = 0; j < 4; ++j) {
                    const float2 f0 = __half22float2(*(__half2*)&cacc[rt][j][0]);
                    const float2 f1 = __half22float2(*(__half2*)&cacc[rt][j][1]);
                    acc[rt][j][0] += f0.x;
                    acc[rt][j][1] += f0.y;
                    acc[rt][j][2] += f1.x;
                    acc[rt][j][3] += f1.y;
                }
        }
    }

    // ---- epilogue: stage accumulators to smem (pitch 33), then coalesced store
    __syncthreads();
    float* ep = (float*)sm;
    const int g  = lane >> 2;
    const int cq = 2 * (lane & 3);
    #pragma unroll
    for (int rt = 0; rt < 4; ++rt) {
        const int R = warp * 64 + rt * 16 + g;
        #pragma unroll
        for (int j = 0; j < 4; ++j) {
            const int col = j * 8 + cq;
            ep[R * 33 + col]           = acc[rt][j][0];
            ep[R * 33 + col + 1]       = acc[rt][j][1];
            ep[(R + 8) * 33 + col]     = acc[rt][j][2];
            ep[(R + 8) * 33 + col + 1] = acc[rt][j][3];
        }
    }
    __syncthreads();

    #pragma unroll
    for (int half = 0; half < 2; ++half) {
        const int r = half * 256 + t;
        const int h = hstart + (r >> 5);
        const int w = r & 31;
        if (w < 30 && h < 30) {
            float* ob = out + (((long)b * 32 * DO_ + d0) * 30 + h) * 30 + w;
            #pragma unroll 8
            for (int co = 0; co < 32; ++co) {
                const float v = ep[r * 33 + co];
                const float y = fmaf(v, e1[co], e0[co]);
                float th; asm("tanh.approx.f32 %0, %1;" : "=f"(th) : "f"(y));
                const float z = th * e2n[co];
                float ex; asm("ex2.approx.f32 %0, %1;" : "=f"(ex) : "f"(z));
                float sg; asm("rcp.approx.f32 %0, %1;" : "=f"(sg) : "f"(1.0f + ex));
                ob[(long)co * (DO_ * 30 * 30)] = sg;
            }
        }
    }
}

// ---------------- launch ----------------
extern "C" void kernel_launch(void* const* d_in, const int* in_sizes, int n_in,
                              void* d_out, int out_size)
{
    const float* x  = (const float*)d_in[0];
    const float* w  = (const float*)d_in[1];
    const float* cb = (const float*)d_in[2];
    const float* sf = (const float*)d_in[3];
    const float* bp = (const float*)d_in[4];
    float* out      = (float*)d_out;

    cudaFuncSetAttribute(conv_main, cudaFuncAttributeMaxDynamicSharedMemorySize, SMEM_DYN);

    xform_all<<<2048 + 54, 256>>>(x, w);

    dim3 grid(DO_, 16, 2);
    conv_main<<<grid, TPB, SMEM_DYN>>>(cb, sf, bp, out);
}